// round 6
// baseline (speedup 1.0000x reference)
#include <cuda_runtime.h>
#include <cuda_fp16.h>
#include <cstdint>

#define NPTS 100000
#define CIN  96
#define CHID 576
#define COUT 96
#define TME  64           // expand tile
#define TM   32           // fused tile (100000 = 3125 * 32, no tail)
#define LDX  584          // x2s stride (halves): 1168B row -> ldmatrix conflict-free
#define FS   120          // feats tile stride (halves)
#define XS4  100          // expand staging stride (floats)
#define NBLKE ((NPTS + TME - 1) / TME)   // 1563
#define NBLKF (NPTS / TM)                // 3125 exact

// ---------------- device scratch ----------------
__device__ float  g_x1[(size_t)NPTS * CHID];      // stage-1 activations (fp32, exact)
__device__ uint2  g_w1f[6  * 72 * 32];            // w1 B-fragments [ka][na][lane]
__device__ uint2  g_w3f[36 * 12 * 32];            // w3 B-fragments [ka][na][lane]

// ---------------- helpers ----------------
__device__ __forceinline__ void ldmatrix_x4(uint32_t* r, uint32_t saddr) {
    asm volatile("ldmatrix.sync.aligned.m8n8.x4.shared.b16 {%0,%1,%2,%3}, [%4];"
                 : "=r"(r[0]), "=r"(r[1]), "=r"(r[2]), "=r"(r[3]) : "r"(saddr));
}
__device__ __forceinline__ void mma16816(float* c, const uint32_t* a, const uint32_t* b) {
    asm volatile("mma.sync.aligned.m16n8k16.row.col.f32.f16.f16.f32 "
                 "{%0,%1,%2,%3}, {%4,%5,%6,%7}, {%8,%9}, {%0,%1,%2,%3};"
                 : "+f"(c[0]), "+f"(c[1]), "+f"(c[2]), "+f"(c[3])
                 : "r"(a[0]), "r"(a[1]), "r"(a[2]), "r"(a[3]), "r"(b[0]), "r"(b[1]));
}
__device__ __forceinline__ uint32_t pack2(float lo, float hi) {
    __half2 h = __floats2half2_rn(lo, hi);
    return *(uint32_t*)&h;
}
__device__ __forceinline__ unsigned long long pk64(float lo, float hi) {
    unsigned long long v;
    asm("mov.b64 %0, {%1, %2};" : "=l"(v) : "f"(lo), "f"(hi));
    return v;
}
__device__ __forceinline__ void upk64(float& lo, float& hi, unsigned long long v) {
    asm("mov.b64 {%0, %1}, %2;" : "=f"(lo), "=f"(hi) : "l"(v));
}
__device__ __forceinline__ void ffma2(unsigned long long& acc, unsigned long long a, unsigned long long b) {
    asm("fma.rn.f32x2 %0, %1, %2, %0;" : "+l"(acc) : "l"(a), "l"(b));
}
__device__ __forceinline__ unsigned long long fmul2(unsigned long long a, unsigned long long b) {
    unsigned long long o;
    asm("mul.rn.f32x2 %0, %1, %2;" : "=l"(o) : "l"(a), "l"(b));
    return o;
}

// ---------------- merged weight-fragment pack ----------------
__global__ void pack_wf(const float* __restrict__ w1, const float* __restrict__ w3) {
    int idx = blockIdx.x * blockDim.x + threadIdx.x;
    if (idx < 6 * 72 * 32) {
        int lane = idx & 31, na = (idx >> 5) % 72, ka = idx / (32 * 72);
        int k0 = ka * 16 + (lane & 3) * 2;
        int n  = na * 8 + (lane >> 2);
        uint2 v;
        v.x = pack2(w1[k0 * CHID + n],       w1[(k0 + 1) * CHID + n]);
        v.y = pack2(w1[(k0 + 8) * CHID + n], w1[(k0 + 9) * CHID + n]);
        g_w1f[idx] = v;
    } else {
        int j = idx - 6 * 72 * 32;
        if (j >= 36 * 12 * 32) return;
        int lane = j & 31, na = (j >> 5) % 12, ka = j / (32 * 12);
        int k0 = ka * 16 + (lane & 3) * 2;
        int n  = na * 8 + (lane >> 2);
        uint2 v;
        v.x = pack2(w3[k0 * COUT + n],       w3[(k0 + 1) * COUT + n]);
        v.y = pack2(w3[(k0 + 8) * COUT + n], w3[(k0 + 9) * COUT + n]);
        g_w3f[j] = v;
    }
}

// ---------------- stage 1: 1x1 expand (HMMA, bit-exact) ----------------
__global__ __launch_bounds__(256, 3) void expand_kernel(
    const float* __restrict__ feats,
    const float* __restrict__ b1, const float* __restrict__ s1) {
    __shared__ __align__(16) __half sfeat[TME * FS];
    __shared__ __align__(16) float sxout[TME * XS4];
    __shared__ float sb1[CHID], ss1[CHID];
    int t = threadIdx.x;
    int site0 = blockIdx.x * TME;

    #pragma unroll
    for (int it = 0; it < 12; it++) {
        int i = t + it * 256;
        int s = i / 48, c2 = i - s * 48;
        uint32_t v = 0;
        if (site0 + s < NPTS) {
            float2 f = *(const float2*)(feats + (size_t)(site0 + s) * CIN + 2 * c2);
            v = pack2(f.x, f.y);
        }
        *(uint32_t*)&sfeat[s * FS + 2 * c2] = v;
    }
    for (int i = t; i < CHID; i += 256) {
        sb1[i] = b1[i];
        ss1[i] = rintf(s1[i]) * (1.0f / 256.0f);
    }
    __syncthreads();

    int warp = t >> 5, lane = t & 31;
    int mbase = (warp & 1) * 32;
    int natom0 = (warp >> 1) * 3;
    uint32_t sbase = (uint32_t)__cvta_generic_to_shared(sfeat);
    int r = lane >> 2, cl = (lane & 3) * 2;

    for (int c = 0; c < 6; c++) {
        float acc[2][3][4];
        #pragma unroll
        for (int mi = 0; mi < 2; mi++)
            #pragma unroll
            for (int ni = 0; ni < 3; ni++)
                #pragma unroll
                for (int j = 0; j < 4; j++) acc[mi][ni][j] = 0.0f;
        #pragma unroll
        for (int ka = 0; ka < 6; ka++) {
            uint32_t a[2][4];
            #pragma unroll
            for (int mi = 0; mi < 2; mi++) {
                int row = mbase + mi * 16 + (lane & 15);
                ldmatrix_x4(a[mi], sbase + (row * FS + ka * 16 + (lane >> 4) * 8) * 2);
            }
            uint2 b[3];
            #pragma unroll
            for (int ni = 0; ni < 3; ni++)
                b[ni] = g_w1f[(ka * 72 + c * 12 + natom0 + ni) * 32 + lane];
            #pragma unroll
            for (int mi = 0; mi < 2; mi++)
                #pragma unroll
                for (int ni = 0; ni < 3; ni++)
                    mma16816(acc[mi][ni], a[mi], (const uint32_t*)&b[ni]);
        }
        #pragma unroll
        for (int ni = 0; ni < 3; ni++) {
            int chl = natom0 * 8 + ni * 8 + cl;
            int ch = c * 96 + chl;
            float rs0 = ss1[ch], rs1 = ss1[ch + 1];
            float bb0 = sb1[ch], bb1 = sb1[ch + 1];
            #pragma unroll
            for (int mi = 0; mi < 2; mi++)
                #pragma unroll
                for (int half = 0; half < 2; half++) {
                    int row = mbase + mi * 16 + r + half * 8;
                    float v0 = fminf(fmaxf((acc[mi][ni][half * 2 + 0] + bb0) * rs0, 0.0f), 6.0f);
                    float v1 = fminf(fmaxf((acc[mi][ni][half * 2 + 1] + bb1) * rs1, 0.0f), 6.0f);
                    float2 p; p.x = v0; p.y = v1;
                    *(float2*)&sxout[row * XS4 + chl] = p;
                }
        }
        __syncthreads();
        // coalesced fp32 write: 64 rows x 384B, 16B lanes (1536 uint4)
        #pragma unroll
        for (int it = 0; it < 6; it++) {
            int i = t + it * 256;
            int row = i / 24, q = i - row * 24;
            if (site0 + row < NPTS) {
                uint4 v = *(uint4*)&sxout[row * XS4 + q * 4];
                *(uint4*)&g_x1[(size_t)(site0 + row) * CHID + c * 96 + q * 4] = v;
            }
        }
        __syncthreads();
    }
}

// ---------------- stage 2+3: fused depthwise + project (HMMA) + residual ----------------
// smem: x2s 37376 + sw2f(8 taps) 18432 + snbr(8 taps) 1024 = 56832 B -> 4 CTAs/SM
#define SMEM_F (TM * LDX * 2 + 8 * CHID * 4 + TM * 8 * 4)

__global__ __launch_bounds__(288, 4) void fused_kernel(
    const int* __restrict__ nbr,
    const float* __restrict__ w2, const float* __restrict__ b2,
    const float* __restrict__ b3,
    const float* __restrict__ s2, const float* __restrict__ s3,
    const float* __restrict__ s_main, const float* __restrict__ s_res,
    const float* __restrict__ feats,
    float* __restrict__ out) {
    extern __shared__ __align__(16) char smraw[];
    __half* x2s   = (__half*)smraw;                 // [32][584]
    float*  sw2f  = (float*)(x2s + TM * LDX);       // [8][576] fp32 (taps 0-3,5-8)
    int*    snbrp = (int*)(sw2f + 8 * CHID);        // [32][8] site-major (non-center taps)

    int t = threadIdx.x;
    int site0 = blockIdx.x * TM;

    for (int i = t; i < 8 * CHID; i += 288) {
        int rr = i / CHID, c = i - rr * CHID;
        sw2f[i] = w2[(rr + (rr >= 4)) * CHID + c];
    }
    if (t < TM * 8) {
        int k8 = t >> 5, s = t & 31;                // coalesced over s per tap
        snbrp[s * 8 + k8] = nbr[(k8 + (k8 >= 4)) * NPTS + site0 + s];
    }
    __syncthreads();

    // ---- Phase A: depthwise 3x3 gather; thread = 4 channels x 16 sites ----
    {
        int g = t % 144, sh = t / 144;
        int cq = g * 4;
        const float* x1cq = g_x1 + cq;
        float4 bq = *(const float4*)(b2 + cq);
        float4 sq = *(const float4*)(s2 + cq);
        float4 wc = *(const float4*)(w2 + 4 * CHID + cq);   // center-tap weights (regs)
        unsigned long long wc01 = pk64(wc.x, wc.y), wc23 = pk64(wc.z, wc.w);
        unsigned long long b01 = pk64(bq.x, bq.y), b23 = pk64(bq.z, bq.w);
        unsigned long long r01 = pk64(rintf(sq.x) * (1.0f / 256.0f), rintf(sq.y) * (1.0f / 256.0f));
        unsigned long long r23 = pk64(rintf(sq.z) * (1.0f / 256.0f), rintf(sq.w) * (1.0f / 256.0f));
        const float* wg = sw2f + cq;

        #pragma unroll 2
        for (int s = 0; s < 16; s++) {
            int site = sh * 16 + s;
            int4 na = *(const int4*)&snbrp[site * 8];
            int4 nb = *(const int4*)&snbrp[site * 8 + 4];
            // center tap: always valid, index = site0 + site (no branch)
            float4 vc = *(const float4*)(x1cq + (size_t)(site0 + site) * CHID);
            unsigned long long a01 = b01, a23 = b23;
            ffma2(a01, pk64(vc.x, vc.y), wc01);
            ffma2(a23, pk64(vc.z, vc.w), wc23);
            #define TAP(J, K) do { int _j = (J); if (_j >= 0) { \
                float4 v = *(const float4*)(x1cq + (size_t)_j * CHID); \
                float4 w = *(const float4*)(wg + (K) * CHID); \
                ffma2(a01, pk64(v.x, v.y), pk64(w.x, w.y)); \
                ffma2(a23, pk64(v.z, v.w), pk64(w.z, w.w)); } } while (0)
            TAP(na.x, 0); TAP(na.y, 1); TAP(na.z, 2); TAP(na.w, 3);
            TAP(nb.x, 4); TAP(nb.y, 5); TAP(nb.z, 6); TAP(nb.w, 7);
            #undef TAP
            a01 = fmul2(a01, r01);
            a23 = fmul2(a23, r23);
            float v0, v1, v2, v3;
            upk64(v0, v1, a01); upk64(v2, v3, a23);
            v0 = fminf(fmaxf(v0, 0.f), 6.f); v1 = fminf(fmaxf(v1, 0.f), 6.f);
            v2 = fminf(fmaxf(v2, 0.f), 6.f); v3 = fminf(fmaxf(v3, 0.f), 6.f);
            uint2 pr; pr.x = pack2(v0, v1); pr.y = pack2(v2, v3);
            *(uint2*)&x2s[site * LDX + cq] = pr;
        }
    }
    __syncthreads();

    // ---- Phase B: project GEMM [32x576]@[576x96] via HMMA (warps 0..7) ----
    int warp = t >> 5, lane = t & 31;
    if (warp < 8) {
        int mbase = (warp & 1) * 16;
        int natom0 = (warp >> 1) * 3;
        uint32_t sbase = (uint32_t)__cvta_generic_to_shared(x2s);

        float acc[3][4];
        #pragma unroll
        for (int ni = 0; ni < 3; ni++)
            #pragma unroll
            for (int j = 0; j < 4; j++) acc[ni][j] = 0.0f;

        #pragma unroll 3
        for (int ka = 0; ka < 36; ka++) {
            uint32_t a[4];
            ldmatrix_x4(a, sbase + ((mbase + (lane & 15)) * LDX + ka * 16 + (lane >> 4) * 8) * 2);
            uint2 b[3];
            #pragma unroll
            for (int ni = 0; ni < 3; ni++)
                b[ni] = g_w3f[(ka * 12 + natom0 + ni) * 32 + lane];
            #pragma unroll
            for (int ni = 0; ni < 3; ni++)
                mma16816(acc[ni], a, (const uint32_t*)&b[ni]);
        }

        float smain = rintf(s_main[0]) * 256.0f;
        float sres  = rintf(s_res[0]) * 256.0f;
        int r = lane >> 2, cl = (lane & 3) * 2;
        #pragma unroll
        for (int ni = 0; ni < 3; ni++) {
            int co = natom0 * 8 + ni * 8 + cl;
            float rs0 = rintf(s3[co]) * (1.0f / 256.0f);
            float rs1 = rintf(s3[co + 1]) * (1.0f / 256.0f);
            float bb0 = b3[co], bb1 = b3[co + 1];
            #pragma unroll
            for (int half = 0; half < 2; half++) {
                int site = site0 + mbase + r + half * 8;
                float v0 = (acc[ni][half * 2 + 0] + bb0) * rs0;
                float v1 = (acc[ni][half * 2 + 1] + bb1) * rs1;
                v0 = fminf(fmaxf(v0, -128.0f), 128.0f);
                v1 = fminf(fmaxf(v1, -128.0f), 128.0f);
                float2 fr = *(const float2*)(feats + (size_t)site * CIN + co);
                float2 o;
                o.x = smain * v0 + sres * fr.x;
                o.y = smain * v1 + sres * fr.y;
                *(float2*)(out + (size_t)site * COUT + co) = o;
            }
        }
    }
}

// ---------------- launch ----------------
extern "C" void kernel_launch(void* const* d_in, const int* in_sizes, int n_in,
                              void* d_out, int out_size) {
    const float* feats = (const float*)d_in[0];
    const int*   nbr   = (const int*)d_in[1];
    const float* w1    = (const float*)d_in[2];
    const float* b1    = (const float*)d_in[3];
    const float* w2    = (const float*)d_in[4];
    const float* b2    = (const float*)d_in[5];
    const float* w3    = (const float*)d_in[6];
    const float* b3    = (const float*)d_in[7];
    const float* s1    = (const float*)d_in[8];
    const float* s2    = (const float*)d_in[9];
    const float* s3    = (const float*)d_in[10];
    const float* sm_   = (const float*)d_in[11];
    const float* sr_   = (const float*)d_in[12];
    float* out = (float*)d_out;

    cudaFuncSetAttribute(fused_kernel, cudaFuncAttributeMaxDynamicSharedMemorySize, SMEM_F);

    pack_wf<<<(6 * 72 * 32 + 36 * 12 * 32 + 255) / 256, 256>>>(w1, w3);
    expand_kernel<<<NBLKE, 256>>>(feats, b1, s1);
    fused_kernel<<<NBLKF, 288, SMEM_F>>>(nbr, w2, b2, b3, s2, s3, sm_, sr_, feats, out);
}

// round 7
// speedup vs baseline: 1.1662x; 1.1662x over previous
#include <cuda_runtime.h>
#include <cuda_fp16.h>
#include <cstdint>

#define NPTS 100000
#define CIN  96
#define CHID 576
#define COUT 96
#define TME  64           // expand tile
#define TM   32           // fused tile (100000 = 3125 * 32, no tail)
#define LDX  584          // x2s stride (halves): 1168B row -> ldmatrix conflict-free
#define FS   120          // feats tile stride (halves)
#define XS   104          // expand staging stride (halves)
#define NBLKE ((NPTS + TME - 1) / TME)   // 1563
#define NBLKF (NPTS / TM)                // 3125 exact

// ---------------- device scratch ----------------
__device__ __half g_x1[(size_t)NPTS * CHID];      // stage-1 activations (fp16, exact)
__device__ uint2  g_w1f[6  * 72 * 32];            // w1 B-fragments [ka][na][lane]
__device__ uint2  g_w3f[36 * 12 * 32];            // w3 B-fragments [ka][na][lane]

// ---------------- helpers ----------------
__device__ __forceinline__ void ldmatrix_x4(uint32_t* r, uint32_t saddr) {
    asm volatile("ldmatrix.sync.aligned.m8n8.x4.shared.b16 {%0,%1,%2,%3}, [%4];"
                 : "=r"(r[0]), "=r"(r[1]), "=r"(r[2]), "=r"(r[3]) : "r"(saddr));
}
__device__ __forceinline__ void mma16816(float* c, const uint32_t* a, const uint32_t* b) {
    asm volatile("mma.sync.aligned.m16n8k16.row.col.f32.f16.f16.f32 "
                 "{%0,%1,%2,%3}, {%4,%5,%6,%7}, {%8,%9}, {%0,%1,%2,%3};"
                 : "+f"(c[0]), "+f"(c[1]), "+f"(c[2]), "+f"(c[3])
                 : "r"(a[0]), "r"(a[1]), "r"(a[2]), "r"(a[3]), "r"(b[0]), "r"(b[1]));
}
__device__ __forceinline__ uint32_t pack2(float lo, float hi) {
    __half2 h = __floats2half2_rn(lo, hi);
    return *(uint32_t*)&h;
}
__device__ __forceinline__ unsigned long long pk64(float lo, float hi) {
    unsigned long long v;
    asm("mov.b64 %0, {%1, %2};" : "=l"(v) : "f"(lo), "f"(hi));
    return v;
}
__device__ __forceinline__ void upk64(float& lo, float& hi, unsigned long long v) {
    asm("mov.b64 {%0, %1}, %2;" : "=f"(lo), "=f"(hi) : "l"(v));
}
__device__ __forceinline__ void ffma2(unsigned long long& acc, unsigned long long a, unsigned long long b) {
    asm("fma.rn.f32x2 %0, %1, %2, %0;" : "+l"(acc) : "l"(a), "l"(b));
}
__device__ __forceinline__ unsigned long long h2tof2(uint32_t h) {
    float2 f = __half22float2(*(__half2*)&h);
    return pk64(f.x, f.y);
}

// ---------------- merged weight-fragment pack ----------------
__global__ void pack_wf(const float* __restrict__ w1, const float* __restrict__ w3) {
    int idx = blockIdx.x * blockDim.x + threadIdx.x;
    if (idx < 6 * 72 * 32) {
        int lane = idx & 31, na = (idx >> 5) % 72, ka = idx / (32 * 72);
        int k0 = ka * 16 + (lane & 3) * 2;
        int n  = na * 8 + (lane >> 2);
        uint2 v;
        v.x = pack2(w1[k0 * CHID + n],       w1[(k0 + 1) * CHID + n]);
        v.y = pack2(w1[(k0 + 8) * CHID + n], w1[(k0 + 9) * CHID + n]);
        g_w1f[idx] = v;
    } else {
        int j = idx - 6 * 72 * 32;
        if (j >= 36 * 12 * 32) return;
        int lane = j & 31, na = (j >> 5) % 12, ka = j / (32 * 12);
        int k0 = ka * 16 + (lane & 3) * 2;
        int n  = na * 8 + (lane >> 2);
        uint2 v;
        v.x = pack2(w3[k0 * COUT + n],       w3[(k0 + 1) * COUT + n]);
        v.y = pack2(w3[(k0 + 8) * COUT + n], w3[(k0 + 9) * COUT + n]);
        g_w3f[j] = v;
    }
}

// ---------------- stage 1: 1x1 expand (HMMA, bit-exact) ----------------
__global__ __launch_bounds__(256, 3) void expand_kernel(
    const float* __restrict__ feats,
    const float* __restrict__ b1, const float* __restrict__ s1) {
    __shared__ __align__(16) __half sfeat[TME * FS];
    __shared__ __align__(16) __half sxout[TME * XS];
    __shared__ float sb1[CHID], ss1[CHID];
    int t = threadIdx.x;
    int site0 = blockIdx.x * TME;

    #pragma unroll
    for (int it = 0; it < 12; it++) {
        int i = t + it * 256;
        int s = i / 48, c2 = i - s * 48;
        uint32_t v = 0;
        if (site0 + s < NPTS) {
            float2 f = *(const float2*)(feats + (size_t)(site0 + s) * CIN + 2 * c2);
            v = pack2(f.x, f.y);
        }
        *(uint32_t*)&sfeat[s * FS + 2 * c2] = v;
    }
    for (int i = t; i < CHID; i += 256) {
        sb1[i] = b1[i];
        ss1[i] = rintf(s1[i]) * (1.0f / 256.0f);
    }
    __syncthreads();

    int warp = t >> 5, lane = t & 31;
    int mbase = (warp & 1) * 32;
    int natom0 = (warp >> 1) * 3;
    uint32_t sbase = (uint32_t)__cvta_generic_to_shared(sfeat);
    int r = lane >> 2, cl = (lane & 3) * 2;

    for (int c = 0; c < 6; c++) {
        float acc[2][3][4];
        #pragma unroll
        for (int mi = 0; mi < 2; mi++)
            #pragma unroll
            for (int ni = 0; ni < 3; ni++)
                #pragma unroll
                for (int j = 0; j < 4; j++) acc[mi][ni][j] = 0.0f;
        #pragma unroll
        for (int ka = 0; ka < 6; ka++) {
            uint32_t a[2][4];
            #pragma unroll
            for (int mi = 0; mi < 2; mi++) {
                int row = mbase + mi * 16 + (lane & 15);
                ldmatrix_x4(a[mi], sbase + (row * FS + ka * 16 + (lane >> 4) * 8) * 2);
            }
            uint2 b[3];
            #pragma unroll
            for (int ni = 0; ni < 3; ni++)
                b[ni] = g_w1f[(ka * 72 + c * 12 + natom0 + ni) * 32 + lane];
            #pragma unroll
            for (int mi = 0; mi < 2; mi++)
                #pragma unroll
                for (int ni = 0; ni < 3; ni++)
                    mma16816(acc[mi][ni], a[mi], (const uint32_t*)&b[ni]);
        }
        #pragma unroll
        for (int ni = 0; ni < 3; ni++) {
            int chl = natom0 * 8 + ni * 8 + cl;
            int ch = c * 96 + chl;
            float rs0 = ss1[ch], rs1 = ss1[ch + 1];
            float bb0 = sb1[ch], bb1 = sb1[ch + 1];
            #pragma unroll
            for (int mi = 0; mi < 2; mi++)
                #pragma unroll
                for (int half = 0; half < 2; half++) {
                    int row = mbase + mi * 16 + r + half * 8;
                    float v0 = fminf(fmaxf((acc[mi][ni][half * 2 + 0] + bb0) * rs0, 0.0f), 6.0f);
                    float v1 = fminf(fmaxf((acc[mi][ni][half * 2 + 1] + bb1) * rs1, 0.0f), 6.0f);
                    *(uint32_t*)&sxout[row * XS + chl] = pack2(v0, v1);
                }
        }
        __syncthreads();
        #pragma unroll
        for (int it = 0; it < 3; it++) {
            int i = t + it * 256;
            int row = i / 12, q = i - row * 12;
            if (site0 + row < NPTS) {
                uint4 v = *(uint4*)&sxout[row * XS + q * 8];
                *(uint4*)&g_x1[(size_t)(site0 + row) * CHID + c * 96 + q * 8] = v;
            }
        }
        __syncthreads();
    }
}

// ---------------- stage 2+3: fused depthwise + project (HMMA) + residual ----------------
// smem: x2s 37376 + sw2f(8 taps, pre-scaled) 18432 + snbr offsets 1024 = 56832 B -> 4 CTAs/SM
#define SMEM_F (TM * LDX * 2 + 8 * CHID * 4 + TM * 8 * 4)

__global__ __launch_bounds__(288, 4) void fused_kernel(
    const int* __restrict__ nbr,
    const float* __restrict__ w2, const float* __restrict__ b2,
    const float* __restrict__ b3,
    const float* __restrict__ s2, const float* __restrict__ s3,
    const float* __restrict__ s_main, const float* __restrict__ s_res,
    const float* __restrict__ feats,
    float* __restrict__ out) {
    extern __shared__ __align__(16) char smraw[];
    __half* x2s   = (__half*)smraw;                 // [32][584]
    float*  sw2f  = (float*)(x2s + TM * LDX);       // [8][576] fp32, pre-scaled by r2 (taps 0-3,5-8)
    int*    snbrp = (int*)(sw2f + 8 * CHID);        // [32][8] byte offsets, -1 = invalid

    int t = threadIdx.x;
    int site0 = blockIdx.x * TM;

    for (int i = t; i < 8 * CHID; i += 288) {
        int rr = i / CHID, c = i - rr * CHID;
        // fold requant scale into weights: exact (int * int / 256)
        sw2f[i] = w2[(rr + (rr >= 4)) * CHID + c] * (rintf(s2[c]) * (1.0f / 256.0f));
    }
    if (t < TM * 8) {
        int k8 = t >> 5, s = t & 31;                // coalesced over s per tap
        int j = nbr[(k8 + (k8 >= 4)) * NPTS + site0 + s];
        snbrp[s * 8 + k8] = (j >= 0) ? j * (CHID * 2) : -1;
    }
    __syncthreads();

    // ---- Phase A: depthwise 3x3 gather; thread = 8 channels x 8 sites ----
    {
        int g = t % 72, sq = t / 72;
        int cq = g * 8;
        const char* x1cq = (const char*)(g_x1 + cq);
        // pre-scaled center weights + bias (8 regs each)
        float4 s2a = *(const float4*)(s2 + cq);
        float4 s2b = *(const float4*)(s2 + cq + 4);
        float r0 = rintf(s2a.x) * (1.0f / 256.0f), r1 = rintf(s2a.y) * (1.0f / 256.0f);
        float r2 = rintf(s2a.z) * (1.0f / 256.0f), r3 = rintf(s2a.w) * (1.0f / 256.0f);
        float r4 = rintf(s2b.x) * (1.0f / 256.0f), r5 = rintf(s2b.y) * (1.0f / 256.0f);
        float r6 = rintf(s2b.z) * (1.0f / 256.0f), r7 = rintf(s2b.w) * (1.0f / 256.0f);
        float4 wca = *(const float4*)(w2 + 4 * CHID + cq);
        float4 wcb = *(const float4*)(w2 + 4 * CHID + cq + 4);
        unsigned long long wc01 = pk64(wca.x * r0, wca.y * r1);
        unsigned long long wc23 = pk64(wca.z * r2, wca.w * r3);
        unsigned long long wc45 = pk64(wcb.x * r4, wcb.y * r5);
        unsigned long long wc67 = pk64(wcb.z * r6, wcb.w * r7);
        float4 bqa = *(const float4*)(b2 + cq);
        float4 bqb = *(const float4*)(b2 + cq + 4);
        unsigned long long b01 = pk64(bqa.x * r0, bqa.y * r1);
        unsigned long long b23 = pk64(bqa.z * r2, bqa.w * r3);
        unsigned long long b45 = pk64(bqb.x * r4, bqb.y * r5);
        unsigned long long b67 = pk64(bqb.z * r6, bqb.w * r7);
        const float* wg = sw2f + cq;

        #pragma unroll 2
        for (int s = 0; s < 8; s++) {
            int site = sq * 8 + s;
            int4 na = *(const int4*)&snbrp[site * 8];
            int4 nb = *(const int4*)&snbrp[site * 8 + 4];
            // center tap: always valid, row = site0 + site
            uint4 vc = *(const uint4*)(x1cq + (size_t)(site0 + site) * (CHID * 2));
            unsigned long long a01 = b01, a23 = b23, a45 = b45, a67 = b67;
            ffma2(a01, h2tof2(vc.x), wc01);
            ffma2(a23, h2tof2(vc.y), wc23);
            ffma2(a45, h2tof2(vc.z), wc45);
            ffma2(a67, h2tof2(vc.w), wc67);
            #define TAP8(OFF, K) do { int _o = (OFF); if (_o >= 0) { \
                uint4 v = *(const uint4*)(x1cq + _o); \
                float4 w0 = *(const float4*)(wg + (K) * CHID); \
                float4 w1 = *(const float4*)(wg + (K) * CHID + 4); \
                ffma2(a01, h2tof2(v.x), pk64(w0.x, w0.y)); \
                ffma2(a23, h2tof2(v.y), pk64(w0.z, w0.w)); \
                ffma2(a45, h2tof2(v.z), pk64(w1.x, w1.y)); \
                ffma2(a67, h2tof2(v.w), pk64(w1.z, w1.w)); } } while (0)
            TAP8(na.x, 0); TAP8(na.y, 1); TAP8(na.z, 2); TAP8(na.w, 3);
            TAP8(nb.x, 4); TAP8(nb.y, 5); TAP8(nb.z, 6); TAP8(nb.w, 7);
            #undef TAP8
            float v0, v1, v2, v3, v4, v5, v6, v7;
            upk64(v0, v1, a01); upk64(v2, v3, a23);
            upk64(v4, v5, a45); upk64(v6, v7, a67);
            v0 = fminf(fmaxf(v0, 0.f), 6.f); v1 = fminf(fmaxf(v1, 0.f), 6.f);
            v2 = fminf(fmaxf(v2, 0.f), 6.f); v3 = fminf(fmaxf(v3, 0.f), 6.f);
            v4 = fminf(fmaxf(v4, 0.f), 6.f); v5 = fminf(fmaxf(v5, 0.f), 6.f);
            v6 = fminf(fmaxf(v6, 0.f), 6.f); v7 = fminf(fmaxf(v7, 0.f), 6.f);
            uint4 pr;
            pr.x = pack2(v0, v1); pr.y = pack2(v2, v3);
            pr.z = pack2(v4, v5); pr.w = pack2(v6, v7);
            *(uint4*)&x2s[site * LDX + cq] = pr;
        }
    }
    __syncthreads();

    // ---- Phase B: project GEMM [32x576]@[576x96] via HMMA (warps 0..7) ----
    int warp = t >> 5, lane = t & 31;
    if (warp < 8) {
        int mbase = (warp & 1) * 16;
        int natom0 = (warp >> 1) * 3;
        uint32_t sbase = (uint32_t)__cvta_generic_to_shared(x2s);

        float acc[3][4];
        #pragma unroll
        for (int ni = 0; ni < 3; ni++)
            #pragma unroll
            for (int j = 0; j < 4; j++) acc[ni][j] = 0.0f;

        #pragma unroll 3
        for (int ka = 0; ka < 36; ka++) {
            uint32_t a[4];
            ldmatrix_x4(a, sbase + ((mbase + (lane & 15)) * LDX + ka * 16 + (lane >> 4) * 8) * 2);
            uint2 b[3];
            #pragma unroll
            for (int ni = 0; ni < 3; ni++)
                b[ni] = g_w3f[(ka * 12 + natom0 + ni) * 32 + lane];
            #pragma unroll
            for (int ni = 0; ni < 3; ni++)
                mma16816(acc[ni], a, (const uint32_t*)&b[ni]);
        }

        float smain = rintf(s_main[0]) * 256.0f;
        float sres  = rintf(s_res[0]) * 256.0f;
        int r = lane >> 2, cl = (lane & 3) * 2;
        #pragma unroll
        for (int ni = 0; ni < 3; ni++) {
            int co = natom0 * 8 + ni * 8 + cl;
            float rs0 = rintf(s3[co]) * (1.0f / 256.0f);
            float rs1 = rintf(s3[co + 1]) * (1.0f / 256.0f);
            float bb0 = b3[co], bb1 = b3[co + 1];
            #pragma unroll
            for (int half = 0; half < 2; half++) {
                int site = site0 + mbase + r + half * 8;
                float v0 = (acc[ni][half * 2 + 0] + bb0) * rs0;
                float v1 = (acc[ni][half * 2 + 1] + bb1) * rs1;
                v0 = fminf(fmaxf(v0, -128.0f), 128.0f);
                v1 = fminf(fmaxf(v1, -128.0f), 128.0f);
                float2 fr = *(const float2*)(feats + (size_t)site * CIN + co);
                float2 o;
                o.x = smain * v0 + sres * fr.x;
                o.y = smain * v1 + sres * fr.y;
                *(float2*)(out + (size_t)site * COUT + co) = o;
            }
        }
    }
}

// ---------------- launch ----------------
extern "C" void kernel_launch(void* const* d_in, const int* in_sizes, int n_in,
                              void* d_out, int out_size) {
    const float* feats = (const float*)d_in[0];
    const int*   nbr   = (const int*)d_in[1];
    const float* w1    = (const float*)d_in[2];
    const float* b1    = (const float*)d_in[3];
    const float* w2    = (const float*)d_in[4];
    const float* b2    = (const float*)d_in[5];
    const float* w3    = (const float*)d_in[6];
    const float* b3    = (const float*)d_in[7];
    const float* s1    = (const float*)d_in[8];
    const float* s2    = (const float*)d_in[9];
    const float* s3    = (const float*)d_in[10];
    const float* sm_   = (const float*)d_in[11];
    const float* sr_   = (const float*)d_in[12];
    float* out = (float*)d_out;

    cudaFuncSetAttribute(fused_kernel, cudaFuncAttributeMaxDynamicSharedMemorySize, SMEM_F);

    pack_wf<<<(6 * 72 * 32 + 36 * 12 * 32 + 255) / 256, 256>>>(w1, w3);
    expand_kernel<<<NBLKE, 256>>>(feats, b1, s1);
    fused_kernel<<<NBLKF, 288, SMEM_F>>>(nbr, w2, b2, b3, s2, s3, sm_, sr_, feats, out);
}

// round 8
// speedup vs baseline: 1.2579x; 1.0786x over previous
#include <cuda_runtime.h>
#include <cuda_fp16.h>
#include <cstdint>

#define NPTS 100000
#define CIN  96
#define CHID 576
#define COUT 96
#define TME  64           // expand tile
#define TM   32           // fused tile (100000 = 3125 * 32, no tail)
#define LDX  584          // x2s stride (halves): 1168B row -> ldmatrix conflict-free
#define FS   120          // feats tile stride (halves)
#define XS   104          // expand staging stride (halves)
#define ROWB (CHID * 2)   // bytes per x1 row
#define NBLKE ((NPTS + TME - 1) / TME)   // 1563
#define NBLKF (NPTS / TM)                // 3125 exact

// ---------------- device scratch ----------------
// row NPTS is a permanent zero row (device globals are zero-initialized, never written)
__device__ __half g_x1[(size_t)(NPTS + 1) * CHID];
__device__ uint2  g_w1f[6  * 72 * 32];            // w1 B-fragments [ka][na][lane]
__device__ uint2  g_w3f[36 * 12 * 32];            // w3 B-fragments [ka][na][lane]

// ---------------- helpers ----------------
__device__ __forceinline__ void ldmatrix_x4(uint32_t* r, uint32_t saddr) {
    asm volatile("ldmatrix.sync.aligned.m8n8.x4.shared.b16 {%0,%1,%2,%3}, [%4];"
                 : "=r"(r[0]), "=r"(r[1]), "=r"(r[2]), "=r"(r[3]) : "r"(saddr));
}
__device__ __forceinline__ void mma16816(float* c, const uint32_t* a, const uint32_t* b) {
    asm volatile("mma.sync.aligned.m16n8k16.row.col.f32.f16.f16.f32 "
                 "{%0,%1,%2,%3}, {%4,%5,%6,%7}, {%8,%9}, {%0,%1,%2,%3};"
                 : "+f"(c[0]), "+f"(c[1]), "+f"(c[2]), "+f"(c[3])
                 : "r"(a[0]), "r"(a[1]), "r"(a[2]), "r"(a[3]), "r"(b[0]), "r"(b[1]));
}
__device__ __forceinline__ uint32_t pack2(float lo, float hi) {
    __half2 h = __floats2half2_rn(lo, hi);
    return *(uint32_t*)&h;
}
__device__ __forceinline__ unsigned long long pk64(float lo, float hi) {
    unsigned long long v;
    asm("mov.b64 %0, {%1, %2};" : "=l"(v) : "f"(lo), "f"(hi));
    return v;
}
__device__ __forceinline__ void upk64(float& lo, float& hi, unsigned long long v) {
    asm("mov.b64 {%0, %1}, %2;" : "=f"(lo), "=f"(hi) : "l"(v));
}
__device__ __forceinline__ void ffma2(unsigned long long& acc, unsigned long long a, unsigned long long b) {
    asm("fma.rn.f32x2 %0, %1, %2, %0;" : "+l"(acc) : "l"(a), "l"(b));
}
__device__ __forceinline__ unsigned long long h2tof2(uint32_t h) {
    float2 f = __half22float2(*(__half2*)&h);
    return pk64(f.x, f.y);
}

// ---------------- merged weight-fragment pack ----------------
__global__ void pack_wf(const float* __restrict__ w1, const float* __restrict__ w3) {
    int idx = blockIdx.x * blockDim.x + threadIdx.x;
    if (idx < 6 * 72 * 32) {
        int lane = idx & 31, na = (idx >> 5) % 72, ka = idx / (32 * 72);
        int k0 = ka * 16 + (lane & 3) * 2;
        int n  = na * 8 + (lane >> 2);
        uint2 v;
        v.x = pack2(w1[k0 * CHID + n],       w1[(k0 + 1) * CHID + n]);
        v.y = pack2(w1[(k0 + 8) * CHID + n], w1[(k0 + 9) * CHID + n]);
        g_w1f[idx] = v;
    } else {
        int j = idx - 6 * 72 * 32;
        if (j >= 36 * 12 * 32) return;
        int lane = j & 31, na = (j >> 5) % 12, ka = j / (32 * 12);
        int k0 = ka * 16 + (lane & 3) * 2;
        int n  = na * 8 + (lane >> 2);
        uint2 v;
        v.x = pack2(w3[k0 * COUT + n],       w3[(k0 + 1) * COUT + n]);
        v.y = pack2(w3[(k0 + 8) * COUT + n], w3[(k0 + 9) * COUT + n]);
        g_w3f[j] = v;
    }
}

// ---------------- stage 1: 1x1 expand (HMMA, bit-exact) ----------------
__global__ __launch_bounds__(256, 3) void expand_kernel(
    const float* __restrict__ feats,
    const float* __restrict__ b1, const float* __restrict__ s1) {
    __shared__ __align__(16) __half sfeat[TME * FS];
    __shared__ __align__(16) __half sxout[TME * XS];
    __shared__ float sb1[CHID], ss1[CHID];
    int t = threadIdx.x;
    int site0 = blockIdx.x * TME;

    #pragma unroll
    for (int it = 0; it < 12; it++) {
        int i = t + it * 256;
        int s = i / 48, c2 = i - s * 48;
        uint32_t v = 0;
        if (site0 + s < NPTS) {
            float2 f = *(const float2*)(feats + (size_t)(site0 + s) * CIN + 2 * c2);
            v = pack2(f.x, f.y);
        }
        *(uint32_t*)&sfeat[s * FS + 2 * c2] = v;
    }
    for (int i = t; i < CHID; i += 256) {
        sb1[i] = b1[i];
        ss1[i] = rintf(s1[i]) * (1.0f / 256.0f);
    }
    __syncthreads();

    int warp = t >> 5, lane = t & 31;
    int mbase = (warp & 1) * 32;
    int natom0 = (warp >> 1) * 3;
    uint32_t sbase = (uint32_t)__cvta_generic_to_shared(sfeat);
    int r = lane >> 2, cl = (lane & 3) * 2;

    for (int c = 0; c < 6; c++) {
        float acc[2][3][4];
        #pragma unroll
        for (int mi = 0; mi < 2; mi++)
            #pragma unroll
            for (int ni = 0; ni < 3; ni++)
                #pragma unroll
                for (int j = 0; j < 4; j++) acc[mi][ni][j] = 0.0f;
        #pragma unroll
        for (int ka = 0; ka < 6; ka++) {
            uint32_t a[2][4];
            #pragma unroll
            for (int mi = 0; mi < 2; mi++) {
                int row = mbase + mi * 16 + (lane & 15);
                ldmatrix_x4(a[mi], sbase + (row * FS + ka * 16 + (lane >> 4) * 8) * 2);
            }
            uint2 b[3];
            #pragma unroll
            for (int ni = 0; ni < 3; ni++)
                b[ni] = g_w1f[(ka * 72 + c * 12 + natom0 + ni) * 32 + lane];
            #pragma unroll
            for (int mi = 0; mi < 2; mi++)
                #pragma unroll
                for (int ni = 0; ni < 3; ni++)
                    mma16816(acc[mi][ni], a[mi], (const uint32_t*)&b[ni]);
        }
        #pragma unroll
        for (int ni = 0; ni < 3; ni++) {
            int chl = natom0 * 8 + ni * 8 + cl;
            int ch = c * 96 + chl;
            float rs0 = ss1[ch], rs1 = ss1[ch + 1];
            float bb0 = sb1[ch], bb1 = sb1[ch + 1];
            #pragma unroll
            for (int mi = 0; mi < 2; mi++)
                #pragma unroll
                for (int half = 0; half < 2; half++) {
                    int row = mbase + mi * 16 + r + half * 8;
                    float v0 = fminf(fmaxf((acc[mi][ni][half * 2 + 0] + bb0) * rs0, 0.0f), 6.0f);
                    float v1 = fminf(fmaxf((acc[mi][ni][half * 2 + 1] + bb1) * rs1, 0.0f), 6.0f);
                    *(uint32_t*)&sxout[row * XS + chl] = pack2(v0, v1);
                }
        }
        __syncthreads();
        #pragma unroll
        for (int it = 0; it < 3; it++) {
            int i = t + it * 256;
            int row = i / 12, q = i - row * 12;
            if (site0 + row < NPTS) {
                uint4 v = *(uint4*)&sxout[row * XS + q * 8];
                *(uint4*)&g_x1[(size_t)(site0 + row) * CHID + c * 96 + q * 8] = v;
            }
        }
        __syncthreads();
    }
}

// ---------------- stage 2+3: fused depthwise + project (HMMA) + residual ----------------
// smem: x2s 37376 + sw2f(8 taps, pre-scaled) 18432 + snbr offsets 1024 = 56832 B -> 4 CTAs/SM
#define SMEM_F (TM * LDX * 2 + 8 * CHID * 4 + TM * 8 * 4)

__global__ __launch_bounds__(288, 4) void fused_kernel(
    const int* __restrict__ nbr,
    const float* __restrict__ w2, const float* __restrict__ b2,
    const float* __restrict__ b3,
    const float* __restrict__ s2, const float* __restrict__ s3,
    const float* __restrict__ s_main, const float* __restrict__ s_res,
    const float* __restrict__ feats,
    float* __restrict__ out) {
    extern __shared__ __align__(16) char smraw[];
    __half* x2s   = (__half*)smraw;                 // [32][584]
    float*  sw2f  = (float*)(x2s + TM * LDX);       // [8][576] fp32, pre-scaled (taps 0-3,5-8)
    int*    snbrp = (int*)(sw2f + 8 * CHID);        // [32][8] byte offsets; invalid -> zero row

    int t = threadIdx.x;
    int site0 = blockIdx.x * TM;

    for (int i = t; i < 8 * CHID; i += 288) {
        int rr = i / CHID, c = i - rr * CHID;
        // fold requant scale into weights (exact: all values multiples of 2^-16 < 2^24)
        sw2f[i] = w2[(rr + (rr >= 4)) * CHID + c] * (rintf(s2[c]) * (1.0f / 256.0f));
    }
    if (t < TM * 8) {
        int k8 = t >> 5, s = t & 31;                // coalesced over s per tap
        int j = nbr[(k8 + (k8 >= 4)) * NPTS + site0 + s];
        snbrp[s * 8 + k8] = ((j >= 0) ? j : NPTS) * ROWB;   // invalid -> zero row
    }
    __syncthreads();

    // ---- Phase A: branch-free depthwise 3x3 gather; thread = 4 channels x 16 sites ----
    {
        int g = t % 144, sh = t / 144;
        int cq = g * 4;
        const char* x1cq = (const char*)(g_x1 + cq);
        float4 sq = *(const float4*)(s2 + cq);
        float r0 = rintf(sq.x) * (1.0f / 256.0f), r1 = rintf(sq.y) * (1.0f / 256.0f);
        float r2v = rintf(sq.z) * (1.0f / 256.0f), r3v = rintf(sq.w) * (1.0f / 256.0f);
        float4 wc = *(const float4*)(w2 + 4 * CHID + cq);   // center-tap weights, pre-scaled
        unsigned long long wc01 = pk64(wc.x * r0, wc.y * r1);
        unsigned long long wc23 = pk64(wc.z * r2v, wc.w * r3v);
        float4 bq = *(const float4*)(b2 + cq);              // bias, pre-scaled
        unsigned long long b01 = pk64(bq.x * r0, bq.y * r1);
        unsigned long long b23 = pk64(bq.z * r2v, bq.w * r3v);
        const float* wg = sw2f + cq;

        #pragma unroll 2
        for (int s = 0; s < 16; s++) {
            int site = sh * 16 + s;
            int4 na = *(const int4*)&snbrp[site * 8];
            int4 nb = *(const int4*)&snbrp[site * 8 + 4];
            // center tap: always valid, row = site0 + site
            uint2 vc = *(const uint2*)(x1cq + (size_t)(site0 + site) * ROWB);
            unsigned long long a01 = b01, a23 = b23;
            ffma2(a01, h2tof2(vc.x), wc01);
            ffma2(a23, h2tof2(vc.y), wc23);
            #define TAP(OFF, K) do { \
                uint2 v = *(const uint2*)(x1cq + (OFF)); \
                float4 w = *(const float4*)(wg + (K) * CHID); \
                ffma2(a01, h2tof2(v.x), pk64(w.x, w.y)); \
                ffma2(a23, h2tof2(v.y), pk64(w.z, w.w)); } while (0)
            TAP(na.x, 0); TAP(na.y, 1); TAP(na.z, 2); TAP(na.w, 3);
            TAP(nb.x, 4); TAP(nb.y, 5); TAP(nb.z, 6); TAP(nb.w, 7);
            #undef TAP
            float v0, v1, v2, v3;
            upk64(v0, v1, a01); upk64(v2, v3, a23);
            v0 = fminf(fmaxf(v0, 0.f), 6.f); v1 = fminf(fmaxf(v1, 0.f), 6.f);
            v2 = fminf(fmaxf(v2, 0.f), 6.f); v3 = fminf(fmaxf(v3, 0.f), 6.f);
            uint2 pr; pr.x = pack2(v0, v1); pr.y = pack2(v2, v3);
            *(uint2*)&x2s[site * LDX + cq] = pr;
        }
    }
    __syncthreads();

    // ---- Phase B: project GEMM [32x576]@[576x96] via HMMA (warps 0..7) ----
    int warp = t >> 5, lane = t & 31;
    if (warp < 8) {
        int mbase = (warp & 1) * 16;
        int natom0 = (warp >> 1) * 3;
        uint32_t sbase = (uint32_t)__cvta_generic_to_shared(x2s);

        float acc[3][4];
        #pragma unroll
        for (int ni = 0; ni < 3; ni++)
            #pragma unroll
            for (int j = 0; j < 4; j++) acc[ni][j] = 0.0f;

        #pragma unroll 3
        for (int ka = 0; ka < 36; ka++) {
            uint32_t a[4];
            ldmatrix_x4(a, sbase + ((mbase + (lane & 15)) * LDX + ka * 16 + (lane >> 4) * 8) * 2);
            uint2 b[3];
            #pragma unroll
            for (int ni = 0; ni < 3; ni++)
                b[ni] = g_w3f[(ka * 12 + natom0 + ni) * 32 + lane];
            #pragma unroll
            for (int ni = 0; ni < 3; ni++)
                mma16816(acc[ni], a, (const uint32_t*)&b[ni]);
        }

        float smain = rintf(s_main[0]) * 256.0f;
        float sres  = rintf(s_res[0]) * 256.0f;
        int r = lane >> 2, cl = (lane & 3) * 2;
        #pragma unroll
        for (int ni = 0; ni < 3; ni++) {
            int co = natom0 * 8 + ni * 8 + cl;
            float rs0 = rintf(s3[co]) * (1.0f / 256.0f);
            float rs1 = rintf(s3[co + 1]) * (1.0f / 256.0f);
            float bb0 = b3[co], bb1 = b3[co + 1];
            #pragma unroll
            for (int half = 0; half < 2; half++) {
                int site = site0 + mbase + r + half * 8;
                float v0 = (acc[ni][half * 2 + 0] + bb0) * rs0;
                float v1 = (acc[ni][half * 2 + 1] + bb1) * rs1;
                v0 = fminf(fmaxf(v0, -128.0f), 128.0f);
                v1 = fminf(fmaxf(v1, -128.0f), 128.0f);
                float2 fr = *(const float2*)(feats + (size_t)site * CIN + co);
                float2 o;
                o.x = smain * v0 + sres * fr.x;
                o.y = smain * v1 + sres * fr.y;
                *(float2*)(out + (size_t)site * COUT + co) = o;
            }
        }
    }
}

// ---------------- launch ----------------
extern "C" void kernel_launch(void* const* d_in, const int* in_sizes, int n_in,
                              void* d_out, int out_size) {
    const float* feats = (const float*)d_in[0];
    const int*   nbr   = (const int*)d_in[1];
    const float* w1    = (const float*)d_in[2];
    const float* b1    = (const float*)d_in[3];
    const float* w2    = (const float*)d_in[4];
    const float* b2    = (const float*)d_in[5];
    const float* w3    = (const float*)d_in[6];
    const float* b3    = (const float*)d_in[7];
    const float* s1    = (const float*)d_in[8];
    const float* s2    = (const float*)d_in[9];
    const float* s3    = (const float*)d_in[10];
    const float* sm_   = (const float*)d_in[11];
    const float* sr_   = (const float*)d_in[12];
    float* out = (float*)d_out;

    cudaFuncSetAttribute(fused_kernel, cudaFuncAttributeMaxDynamicSharedMemorySize, SMEM_F);

    pack_wf<<<(6 * 72 * 32 + 36 * 12 * 32 + 255) / 256, 256>>>(w1, w3);
    expand_kernel<<<NBLKE, 256>>>(feats, b1, s1);
    fused_kernel<<<NBLKF, 288, SMEM_F>>>(nbr, w2, b2, b3, s2, s3, sm_, sr_, feats, out);
}